// round 2
// baseline (speedup 1.0000x reference)
#include <cuda_runtime.h>
#include <cuda_bf16.h>
#include <cstdint>

#define NROWS  100000
#define NFEAT  256
#define NOUT   128
#define NEDGES 3200000

// Scratch for the projected features h = x @ W  (100000 x 128 fp32 = 51.2 MB).
// __device__ global (allocation APIs are forbidden; this is the sanctioned way).
__device__ float g_h[(size_t)NROWS * NOUT];

// ---------------------------------------------------------------------------
// GEMM: h = x @ W.  Block tile 128 rows x 128 cols, K-chunks of 16.
// 256 threads, each computes an 8x8 micro-tile in registers.
// ---------------------------------------------------------------------------
__global__ __launch_bounds__(256, 2)
void gcn_gemm_kernel(const float* __restrict__ x, const float* __restrict__ W) {
    __shared__ float As[16][128];   // [k][row]  (A transposed on store)
    __shared__ float Bs[16][128];   // [k][col]

    const int block_row = blockIdx.x * 128;
    const int t  = threadIdx.x;
    const int tx = t & 15;          // 16 col-groups
    const int ty = t >> 4;          // 16 row-groups

    float acc[8][8];
    #pragma unroll
    for (int i = 0; i < 8; i++)
        #pragma unroll
        for (int j = 0; j < 8; j++)
            acc[i][j] = 0.0f;

    for (int k0 = 0; k0 < NFEAT; k0 += 16) {
        // Load A tile: 128 rows x 16 k  (512 float4 loads, 2 per thread)
        #pragma unroll
        for (int i = 0; i < 2; i++) {
            int idx = t + i * 256;            // 0..511
            int r   = idx >> 2;               // 0..127
            int kk  = (idx & 3) * 4;          // 0,4,8,12
            int grow = block_row + r;
            float4 v = make_float4(0.f, 0.f, 0.f, 0.f);
            if (grow < NROWS)
                v = *(const float4*)(x + (size_t)grow * NFEAT + k0 + kk);
            As[kk + 0][r] = v.x;
            As[kk + 1][r] = v.y;
            As[kk + 2][r] = v.z;
            As[kk + 3][r] = v.w;
        }
        // Load B tile: 16 k x 128 cols (512 float4 loads, 2 per thread)
        #pragma unroll
        for (int i = 0; i < 2; i++) {
            int idx = t + i * 256;            // 0..511
            int kk  = idx >> 5;               // 0..15
            int c   = (idx & 31) * 4;         // 0..124
            float4 v = *(const float4*)(W + (size_t)(k0 + kk) * NOUT + c);
            *(float4*)&Bs[kk][c] = v;
        }
        __syncthreads();

        #pragma unroll
        for (int k = 0; k < 16; k++) {
            float a[8], b[8];
            *(float4*)&a[0] = *(const float4*)&As[k][ty * 8];
            *(float4*)&a[4] = *(const float4*)&As[k][ty * 8 + 4];
            *(float4*)&b[0] = *(const float4*)&Bs[k][tx * 8];
            *(float4*)&b[4] = *(const float4*)&Bs[k][tx * 8 + 4];
            #pragma unroll
            for (int i = 0; i < 8; i++)
                #pragma unroll
                for (int j = 0; j < 8; j++)
                    acc[i][j] += a[i] * b[j];
        }
        __syncthreads();
    }

    // Store h tile
    #pragma unroll
    for (int i = 0; i < 8; i++) {
        int grow = block_row + ty * 8 + i;
        if (grow < NROWS) {
            float* hp = g_h + (size_t)grow * NOUT + tx * 8;
            *(float4*)(hp + 0) = make_float4(acc[i][0], acc[i][1], acc[i][2], acc[i][3]);
            *(float4*)(hp + 4) = make_float4(acc[i][4], acc[i][5], acc[i][6], acc[i][7]);
        }
    }
}

// ---------------------------------------------------------------------------
// SpMM scatter: one warp per edge, grid-stride over edges.
// 32 lanes x float4 = 128 features.
// out[row] += val * h[col]  via vector red.global.add.v4.f32 (no return).
// h and out both ~fit in the ~126 MB L2, so gathers + reductions are
// mostly L2-resident; expect LTS-throughput bound, not DRAM bound.
// ---------------------------------------------------------------------------
__global__ __launch_bounds__(256)
void gcn_spmm_kernel(const float* __restrict__ ev,
                     const int*   __restrict__ er,
                     const int*   __restrict__ ec,
                     float*       __restrict__ out) {
    const int lane       = threadIdx.x & 31;
    const int warp_id    = (blockIdx.x * blockDim.x + threadIdx.x) >> 5;
    const int warp_count = (gridDim.x * blockDim.x) >> 5;

    for (int e = warp_id; e < NEDGES; e += warp_count) {
        const float val = __ldg(ev + e);
        const int   row = __ldg(er + e);
        const int   col = __ldg(ec + e);

        float4 h4 = *(const float4*)(g_h + (size_t)col * NOUT + lane * 4);
        h4.x *= val; h4.y *= val; h4.z *= val; h4.w *= val;

        float* op = out + (size_t)row * NOUT + lane * 4;
        asm volatile("red.global.add.v4.f32 [%0], {%1, %2, %3, %4};"
                     :: "l"(op), "f"(h4.x), "f"(h4.y), "f"(h4.z), "f"(h4.w)
                     : "memory");
    }
}

// ---------------------------------------------------------------------------
// Launch: memset out -> GEMM -> SpMM (all async, graph-capturable,
// allocation-free).
// Inputs (metadata order): x [1,100000,256] f32, W [256,128] f32,
// edge_vals [3.2M] f32, edge_rows [3.2M] i32, edge_cols [3.2M] i32.
// Output: [1,100000,128] f32.
// ---------------------------------------------------------------------------
extern "C" void kernel_launch(void* const* d_in, const int* in_sizes, int n_in,
                              void* d_out, int out_size) {
    const float* x  = (const float*)d_in[0];
    const float* W  = (const float*)d_in[1];
    const float* ev = (const float*)d_in[2];
    const int*   er = (const int*)d_in[3];
    const int*   ec = (const int*)d_in[4];
    float*       out = (float*)d_out;

    cudaMemsetAsync(out, 0, (size_t)out_size * sizeof(float));

    gcn_gemm_kernel<<<(NROWS + 127) / 128, 256>>>(x, W);

    // Grid-stride SpMM: 4096 blocks x 8 warps = 32768 resident warps,
    // ~98 edges per warp.
    gcn_spmm_kernel<<<4096, 256>>>(ev, er, ec, out);
}